// round 2
// baseline (speedup 1.0000x reference)
#include <cuda_runtime.h>
#include <math.h>

#define B_   32
#define C_   768
#define D_   512
#define NH_  4
#define HD_  192
#define FHW_ 576

// ---------------- scratch (device globals; no runtime allocation) ------------
// layout (floats):
static const long OFF_T    = 0;                       // 32*512
static const long OFF_SQ   = OFF_T   + 32L*512;       // 32*4*192
static const long OFF_SK   = OFF_SQ  + 32L*4*192;
static const long OFF_MU1  = OFF_SK  + 32L*4*192;     // 18432
static const long OFF_RS1  = OFF_MU1 + 18432L;
static const long OFF_MU2  = OFF_RS1 + 18432L;
static const long OFF_RS2  = OFF_MU2 + 18432L;
static const long OFF_QKV  = OFF_RS2 + 18432L;        // 32*2304*576
static const long OFF_ATTN = OFF_QKV + 32L*2304*576;  // 32*4*192*576
static const long OFF_IMG  = OFF_ATTN+ 32L*4*192*576; // 32*768*192
static const long OFF_Y    = OFF_IMG + 32L*768*192;   // 32*768*576
static const long OFF_OUT  = OFF_Y   + 32L*768*576;
static const long OFF_Z1   = OFF_OUT + 32L*768*576;
static const long OFF_Z2   = OFF_Z1  + 32L*768*576;
static const long SCR_TOTAL= OFF_Z2  + 32L*768*576;

__device__ float g_scratch[SCR_TOTAL];

// ---------------- txt layernorm -----------------------------------------------
__global__ void txtln_k(const float* __restrict__ T, const float* __restrict__ gw,
                        const float* __restrict__ gb, float* __restrict__ Tn) {
    int b = blockIdx.x, tid = threadIdx.x;
    const float* row = T + (long)b * D_;
    float s = 0.f, ss = 0.f;
    for (int i = tid; i < D_; i += 256) { float v = row[i]; s += v; ss += v * v; }
    for (int o = 16; o; o >>= 1) { s += __shfl_down_sync(0xffffffffu, s, o); ss += __shfl_down_sync(0xffffffffu, ss, o); }
    __shared__ float red[16];
    __shared__ float mr[2];
    int w = tid >> 5;
    if ((tid & 31) == 0) { red[w] = s; red[8 + w] = ss; }
    __syncthreads();
    if (tid == 0) {
        float S = 0.f, S2 = 0.f;
        for (int i = 0; i < 8; i++) { S += red[i]; S2 += red[8 + i]; }
        float m = S / D_;
        float v = S2 / D_ - m * m;
        mr[0] = m; mr[1] = rsqrtf(v + 1e-5f);
    }
    __syncthreads();
    float m = mr[0], r = mr[1];
    for (int i = tid; i < D_; i += 256)
        Tn[(long)b * D_ + i] = (row[i] - m) * r * gw[i] + gb[i];
}

// ---------------- txt qkv projection -> sign factors --------------------------
__global__ void txtqkv_k(const float* __restrict__ Tn, const float* __restrict__ Wq,
                         float* __restrict__ sq, float* __restrict__ sk) {
    int b = blockIdx.x;
    __shared__ float t[512];
    for (int i = threadIdx.x; i < 512; i += 256) t[i] = Tn[(long)b * 512 + i];
    __syncthreads();
    int idx = blockIdx.y * 256 + threadIdx.x;     // 0..1535
    int n = idx / 384, r = idx % 384, part = r / 192, hd = r % 192;
    int o2 = n * 576 + part * 192 + hd;           // reshape (NH,3,HD)
    const float* w = Wq + (long)o2 * 512;
    float acc = 0.f;
    #pragma unroll 8
    for (int k2 = 0; k2 < 512; k2++) acc += t[k2] * w[k2];
    float sgn = acc / fmaxf(fabsf(acc), 1e-12f);
    if (part == 0) sq[(b * 4 + n) * 192 + hd] = sgn;
    else           sk[(b * 4 + n) * 192 + hd] = sgn;
}

// ---------------- per-pixel layernorm stats over C ----------------------------
__global__ void stats_k(const float* __restrict__ X, float* __restrict__ mu,
                        float* __restrict__ rs, float eps) {
    int px0 = blockIdx.x * 32;
    int lane = threadIdx.x & 31, grp = threadIdx.x >> 5;
    int gp = px0 + lane;
    int b = gp / FHW_, p = gp % FHW_;
    const float* base = X + (long)b * C_ * FHW_ + p;
    float s = 0.f, ss = 0.f;
    for (int c = grp; c < C_; c += 8) { float v = base[(long)c * FHW_]; s += v; ss += v * v; }
    __shared__ float Ss[8][32], S2[8][32];
    Ss[grp][lane] = s; S2[grp][lane] = ss;
    __syncthreads();
    if (grp == 0) {
        for (int g = 1; g < 8; g++) { s += Ss[g][lane]; ss += S2[g][lane]; }
        float m = s / C_;
        float v = ss / C_ - m * m;
        mu[gp] = m;
        rs[gp] = rsqrtf(v + eps);
    }
}

// ---------------- generic tiled SGEMM -----------------------------------------
// C[m,n] = sum_k A[m,k] * B[k,n]  (batched via blockIdx.z)
enum { BMODE_PLAIN = 0, BMODE_LN = 1, BMODE_TRANS = 2 };
enum { EPI_NONE = 0, EPI_BIASM = 1, EPI_BIASN = 2, EPI_BIASM_RES = 3, EPI_RES = 4 };

template<int BM, int BN, int BK, int TM, int TN, int BMODE, int EPI>
__global__ void __launch_bounds__(256)
gemm_k(const float* __restrict__ A, const float* __restrict__ Bp, float* __restrict__ Cp,
       int M, int N, int K,
       long sA, long sBout, int divB, long sBin, long sC,
       const float* __restrict__ mu, const float* __restrict__ rs,
       const float* __restrict__ lw, const float* __restrict__ lb,
       const float* __restrict__ biasM, const float* __restrict__ biasN,
       const float* __restrict__ res, long sRes)
{
    static_assert((BM / TM) * (BN / TN) == 256, "thread grid");
    const int bz = blockIdx.z;
    const long offA = sA * bz;
    const long offB = (long)(bz / divB) * sBout + (long)(bz % divB) * sBin;
    const long offC = sC * bz;
    const int n0 = blockIdx.x * BN;
    const int m0 = blockIdx.y * BM;
    const int tid = threadIdx.x;
    const int TXN = BN / TN;
    const int tx = tid % TXN;
    const int ty = tid / TXN;

    __shared__ __align__(16) float As[BK][BM];
    __shared__ __align__(16) float Bs[BK][BN];
    __shared__ float muS[BN], rsS[BN];

    if (BMODE == BMODE_LN) {
        for (int i = tid; i < BN; i += 256) {
            muS[i] = mu[(long)bz * N + n0 + i];
            rsS[i] = rs[(long)bz * N + n0 + i];
        }
        __syncthreads();
    }

    float acc[TM][TN];
    #pragma unroll
    for (int i = 0; i < TM; i++)
        #pragma unroll
        for (int j = 0; j < TN; j++) acc[i][j] = 0.f;

    const int LA = BM * BK / 256;
    const int LB = BK * BN / 256;

    for (int kb = 0; kb < K; kb += BK) {
        #pragma unroll
        for (int i = 0; i < LA; i++) {
            int idx = tid + i * 256;
            int am = idx / BK, ak = idx % BK;
            As[ak][am] = A[offA + (long)(m0 + am) * K + kb + ak];
        }
        if (BMODE == BMODE_TRANS) {
            #pragma unroll
            for (int i = 0; i < LB; i++) {
                int idx = tid + i * 256;
                int bn = idx / BK, bk = idx % BK;
                Bs[bk][bn] = Bp[offB + (long)(n0 + bn) * K + kb + bk];
            }
        } else {
            #pragma unroll
            for (int i = 0; i < LB; i++) {
                int idx = tid + i * 256;
                int bk = idx / BN, bn = idx % BN;
                float x = Bp[offB + (long)(kb + bk) * N + n0 + bn];
                if (BMODE == BMODE_LN) {
                    int c = kb + bk;
                    x = lw[c] * ((x - muS[bn]) * rsS[bn]) + lb[c];
                }
                Bs[bk][bn] = x;
            }
        }
        __syncthreads();

        #pragma unroll
        for (int kk = 0; kk < BK; kk++) {
            float a[TM], bb[TN];
            const float4* ap = reinterpret_cast<const float4*>(&As[kk][ty * TM]);
            #pragma unroll
            for (int i = 0; i < TM / 4; i++) {
                float4 v = ap[i];
                a[4*i] = v.x; a[4*i+1] = v.y; a[4*i+2] = v.z; a[4*i+3] = v.w;
            }
            const float4* bp4 = reinterpret_cast<const float4*>(&Bs[kk][tx * TN]);
            #pragma unroll
            for (int j = 0; j < TN / 4; j++) {
                float4 v = bp4[j];
                bb[4*j] = v.x; bb[4*j+1] = v.y; bb[4*j+2] = v.z; bb[4*j+3] = v.w;
            }
            #pragma unroll
            for (int i = 0; i < TM; i++)
                #pragma unroll
                for (int j = 0; j < TN; j++)
                    acc[i][j] = fmaf(a[i], bb[j], acc[i][j]);
        }
        __syncthreads();
    }

    #pragma unroll
    for (int i = 0; i < TM; i++) {
        int row = m0 + ty * TM + i;
        #pragma unroll
        for (int j = 0; j < TN; j++) {
            int col = n0 + tx * TN + j;
            float v = acc[i][j];
            if (EPI == EPI_BIASM || EPI == EPI_BIASM_RES) v += biasM[row];
            if (EPI == EPI_BIASN) v += biasN[col];
            if (EPI == EPI_BIASM_RES || EPI == EPI_RES)
                v += res[sRes * bz + (long)row * N + col];
            Cp[offC + (long)row * N + col] = v;
        }
    }
}

// ---------------- fused attention rows: softmax(±k/|k|)+softmax(±q/|q|) -------
__device__ __forceinline__ float blockReduce192(float v, int op, float* sh) {
    for (int o = 16; o; o >>= 1) {
        float t = __shfl_down_sync(0xffffffffu, v, o);
        v = op ? fmaxf(v, t) : v + t;
    }
    int w = threadIdx.x >> 5;
    if ((threadIdx.x & 31) == 0) sh[w] = v;
    __syncthreads();
    float r = sh[0];
    for (int i = 1; i < 6; i++) r = op ? fmaxf(r, sh[i]) : r + sh[i];
    __syncthreads();
    return r;
}

__global__ void attn_k(const float* __restrict__ qkv, const float* __restrict__ sq,
                       const float* __restrict__ sk, float* __restrict__ attn) {
    int bid = blockIdx.x;                 // b*768 + n*192 + hd
    int hd = bid % 192, n = (bid / 192) % 4, b = bid / 768;
    const float* qrow = qkv + ((long)b * 2304 + n * 192 + hd) * 576;
    const float* krow = qrow + 768L * 576;
    int tid = threadIdx.x;                // 192 threads, 3 elems each
    float q0 = qrow[tid], q1 = qrow[tid + 192], q2 = qrow[tid + 384];
    float k0 = krow[tid], k1 = krow[tid + 192], k2 = krow[tid + 384];

    __shared__ float sh[6];
    float sumq = blockReduce192(q0*q0 + q1*q1 + q2*q2, 0, sh);
    float sumk = blockReduce192(k0*k0 + k1*k1 + k2*k2, 0, sh);
    float rq = 1.f / fmaxf(sqrtf(sumq), 1e-12f);
    float rk = 1.f / fmaxf(sqrtf(sumk), 1e-12f);
    float sgq = sq[(b * 4 + n) * 192 + hd];
    float sgk = sk[(b * 4 + n) * 192 + hd];

    float a0 = sgq * k0 * rk, a1 = sgq * k1 * rk, a2 = sgq * k2 * rk;
    float c0 = sgk * q0 * rq, c1 = sgk * q1 * rq, c2 = sgk * q2 * rq;

    float M1 = blockReduce192(fmaxf(a0, fmaxf(a1, a2)), 1, sh);
    float e0 = __expf(a0 - M1), e1 = __expf(a1 - M1), e2 = __expf(a2 - M1);
    float S1 = blockReduce192(e0 + e1 + e2, 0, sh);

    float M2 = blockReduce192(fmaxf(c0, fmaxf(c1, c2)), 1, sh);
    float f0 = __expf(c0 - M2), f1 = __expf(c1 - M2), f2 = __expf(c2 - M2);
    float S2 = blockReduce192(f0 + f1 + f2, 0, sh);

    float i1 = 1.f / S1, i2 = 1.f / S2;
    float* o = attn + ((long)(b * 4 + n) * 192 + hd) * 576;
    o[tid]       = e0 * i1 + f0 * i2;
    o[tid + 192] = e1 * i1 + f1 * i2;
    o[tid + 384] = e2 * i1 + f2 * i2;
}

// ---------------- depthwise 3x3 conv + exact GELU -----------------------------
__global__ void dwgelu_k(const float* __restrict__ Z, const float* __restrict__ Wd,
                         float* __restrict__ O) {
    int bc = blockIdx.x;                  // b*768 + c
    int c = bc % 768;
    __shared__ float p[576];
    const float* base = Z + (long)bc * 576;
    for (int i = threadIdx.x; i < 576; i += 256) p[i] = base[i];
    float w[9];
    #pragma unroll
    for (int i = 0; i < 9; i++) w[i] = Wd[c * 9 + i];
    __syncthreads();
    for (int i = threadIdx.x; i < 576; i += 256) {
        int y = i / 24, x = i % 24;
        float acc = 0.f;
        #pragma unroll
        for (int dy = -1; dy <= 1; dy++)
            #pragma unroll
            for (int dx = -1; dx <= 1; dx++) {
                int yy = y + dy, xx = x + dx;
                if (yy >= 0 && yy < 24 && xx >= 0 && xx < 24)
                    acc = fmaf(w[(dy + 1) * 3 + dx + 1], p[yy * 24 + xx], acc);
            }
        O[(long)bc * 576 + i] = 0.5f * acc * (1.f + erff(acc * 0.70710678118654752f));
    }
}

// ---------------- host launch --------------------------------------------------
extern "C" void kernel_launch(void* const* d_in, const int* in_sizes, int n_in,
                              void* d_out, int out_size) {
    const float* img    = (const float*)d_in[0];
    const float* txt    = (const float*)d_in[1];
    const float* fn_w   = (const float*)d_in[2];
    const float* fn_b   = (const float*)d_in[3];
    const float* gn_w   = (const float*)d_in[4];
    const float* gn_b   = (const float*)d_in[5];
    const float* qkv_img_w = (const float*)d_in[6];
    const float* qkv_txt_w = (const float*)d_in[7];
    const float* o_img_w   = (const float*)d_in[8];
    const float* o_img_b   = (const float*)d_in[9];
    const float* o_img2_w  = (const float*)d_in[10];
    const float* o_img2_b  = (const float*)d_in[11];
    const float* ffn_w  = (const float*)d_in[12];
    const float* ffn_b  = (const float*)d_in[13];
    const float* fc1_w  = (const float*)d_in[14];
    const float* dw_w   = (const float*)d_in[15];
    const float* fc2_w  = (const float*)d_in[16];
    float* out_p = (float*)d_out;

    float* scr = nullptr;
    cudaGetSymbolAddress((void**)&scr, g_scratch);
    float* tbuf = scr + OFF_T;
    float* sqb  = scr + OFF_SQ;
    float* skb  = scr + OFF_SK;
    float* mu1  = scr + OFF_MU1;
    float* rs1  = scr + OFF_RS1;
    float* mu2  = scr + OFF_MU2;
    float* rs2  = scr + OFF_RS2;
    float* qkvb = scr + OFF_QKV;
    float* attnb= scr + OFF_ATTN;
    float* imgb = scr + OFF_IMG;
    float* yb   = scr + OFF_Y;
    float* outb = scr + OFF_OUT;
    float* z1   = scr + OFF_Z1;
    float* z2   = scr + OFF_Z2;

    const long sFeat = (long)C_ * FHW_;      // 442368
    const long sQKV  = 3L * C_ * FHW_;       // 1327104
    const long sAttn = (long)HD_ * FHW_;     // 110592
    const long sImg  = (long)C_ * HD_;       // 147456

    // 1. txt layernorm
    txtln_k<<<32, 256>>>(txt, gn_w, gn_b, tbuf);
    // 2. txt qkv -> sign factors
    txtqkv_k<<<dim3(32, 6), 256>>>(tbuf, qkv_txt_w, sqb, skb);
    // 3. img layernorm stats
    stats_k<<<(B_ * FHW_) / 32, 256>>>(img, mu1, rs1, 1e-6f);
    // 4. qkv projection with fused layernorm (M=2304,N=576,K=768, b=32)
    gemm_k<128, 64, 16, 8, 4, BMODE_LN, EPI_NONE><<<dim3(9, 18, 32), 256>>>(
        qkv_img_w, img, qkvb, 3 * C_, FHW_, C_,
        0, sFeat, 1, 0, sQKV,
        mu1, rs1, fn_w, fn_b, nullptr, nullptr, nullptr, 0);
    // 5. attention rows: summed softmax matrices
    attn_k<<<B_ * NH_ * HD_, 192>>>(qkvb, sqb, skb, attnb);
    // 6. (attn1+attn2) @ V^T  (M=192,N=192,K=576, batch=128)
    gemm_k<64, 64, 16, 4, 4, BMODE_TRANS, EPI_NONE><<<dim3(3, 3, 128), 256>>>(
        attnb, qkvb + 2L * C_ * FHW_, imgb, HD_, HD_, FHW_,
        sAttn, sQKV, 4, sAttn, (long)HD_ * HD_,
        nullptr, nullptr, nullptr, nullptr, nullptr, nullptr, nullptr, 0);
    // 7. img @ o_img2_w^T + b2  (M=768,N=576,K=192, b=32)
    gemm_k<128, 64, 16, 8, 4, BMODE_TRANS, EPI_BIASN><<<dim3(9, 6, 32), 256>>>(
        imgb, o_img2_w, yb, C_, FHW_, HD_,
        sImg, 0, 1, 0, sFeat,
        nullptr, nullptr, nullptr, nullptr, nullptr, o_img2_b, nullptr, 0);
    // 8. o_img conv1x1 + bias + residual(img)  -> out
    gemm_k<128, 64, 16, 8, 4, BMODE_PLAIN, EPI_BIASM_RES><<<dim3(9, 6, 32), 256>>>(
        o_img_w, yb, outb, C_, FHW_, C_,
        0, sFeat, 1, 0, sFeat,
        nullptr, nullptr, nullptr, nullptr, o_img_b, nullptr, img, sFeat);
    // 9. ffn layernorm stats on out
    stats_k<<<(B_ * FHW_) / 32, 256>>>(outb, mu2, rs2, 1e-6f);
    // 10. fc1 with fused layernorm
    gemm_k<128, 64, 16, 8, 4, BMODE_LN, EPI_NONE><<<dim3(9, 6, 32), 256>>>(
        fc1_w, outb, z1, C_, FHW_, C_,
        0, sFeat, 1, 0, sFeat,
        mu2, rs2, ffn_w, ffn_b, nullptr, nullptr, nullptr, 0);
    // 11. depthwise 3x3 + exact gelu
    dwgelu_k<<<B_ * C_, 256>>>(z1, dw_w, z2);
    // 12. fc2 + residual(out) -> d_out
    gemm_k<128, 64, 16, 8, 4, BMODE_PLAIN, EPI_RES><<<dim3(9, 6, 32), 256>>>(
        fc2_w, z2, out_p, C_, FHW_, C_,
        0, sFeat, 1, 0, sFeat,
        nullptr, nullptr, nullptr, nullptr, nullptr, nullptr, outb, sFeat);
}

// round 4
// speedup vs baseline: 5.3131x; 5.3131x over previous
#include <cuda_runtime.h>
#include <cuda_bf16.h>
#include <math.h>
#include <stdint.h>

#define B_   32
#define C_   768
#define D_   512
#define NH_  4
#define HD_  192
#define FHW_ 576

// ---------------- device scratch (zero-init, no runtime allocation) ----------
__device__ float g_tbuf[32*512];
__device__ float g_sq[32*4*192], g_sk[32*4*192];
__device__ float g_mu1[18432], g_rs1[18432], g_mu2[18432], g_rs2[18432];
__device__ float g_qk[32L*1536*576];              // q,k fp32 channel-major
__device__ float g_out[32L*768*576];              // attn-block output fp32
__device__ __nv_bfloat16 g_wqkv[2304*768];
__device__ __nv_bfloat16 g_woimg[768*768];
__device__ __nv_bfloat16 g_woimg2[576*192];
__device__ __nv_bfloat16 g_wfc1[768*768];
__device__ __nv_bfloat16 g_wfc2[768*768];
__device__ __nv_bfloat16 g_lnimgT[32L*576*768];   // LN(img) pixel-major
__device__ __nv_bfloat16 g_v[32L*768*576];        // v bf16 channel-major
__device__ __nv_bfloat16 g_attn[128L*256*576];    // attn rows; rows 192..255 stay zero
__device__ __nv_bfloat16 g_img[32L*768*192];
__device__ __nv_bfloat16 g_yT[32L*576*768];       // y pixel-major
__device__ __nv_bfloat16 g_lnoutT[32L*576*768];   // LN(out) pixel-major
__device__ __nv_bfloat16 g_z1[32L*768*576];       // fc1 out channel-major
__device__ __nv_bfloat16 g_z2T[32L*576*768];      // dw+gelu pixel-major

// ---------------- small kernels ----------------------------------------------
__global__ void txtln_k(const float* __restrict__ T, const float* __restrict__ gw,
                        const float* __restrict__ gb) {
    int b = blockIdx.x, tid = threadIdx.x;
    const float* row = T + (long)b * D_;
    float s = 0.f, ss = 0.f;
    for (int i = tid; i < D_; i += 256) { float v = row[i]; s += v; ss += v * v; }
    for (int o = 16; o; o >>= 1) { s += __shfl_down_sync(~0u, s, o); ss += __shfl_down_sync(~0u, ss, o); }
    __shared__ float red[16]; __shared__ float mr[2];
    int w = tid >> 5;
    if ((tid & 31) == 0) { red[w] = s; red[8 + w] = ss; }
    __syncthreads();
    if (tid == 0) {
        float S = 0.f, S2 = 0.f;
        for (int i = 0; i < 8; i++) { S += red[i]; S2 += red[8 + i]; }
        float m = S / D_, v = S2 / D_ - m * m;
        mr[0] = m; mr[1] = rsqrtf(v + 1e-5f);
    }
    __syncthreads();
    float m = mr[0], r = mr[1];
    for (int i = tid; i < D_; i += 256)
        g_tbuf[(long)b * D_ + i] = (row[i] - m) * r * gw[i] + gb[i];
}

__global__ void txtqkv_k(const float* __restrict__ Wq) {
    int b = blockIdx.x;
    __shared__ float t[512];
    for (int i = threadIdx.x; i < 512; i += 256) t[i] = g_tbuf[(long)b * 512 + i];
    __syncthreads();
    int idx = blockIdx.y * 256 + threadIdx.x;
    int n = idx / 384, r = idx % 384, part = r / 192, hd = r % 192;
    const float* w = Wq + (long)(n * 576 + part * 192 + hd) * 512;
    float acc = 0.f;
    #pragma unroll 8
    for (int k2 = 0; k2 < 512; k2++) acc += t[k2] * w[k2];
    float sgn = acc / fmaxf(fabsf(acc), 1e-12f);
    if (part == 0) g_sq[(b * 4 + n) * 192 + hd] = sgn;
    else           g_sk[(b * 4 + n) * 192 + hd] = sgn;
}

template<int SRC>
__global__ void stats_k(const float* __restrict__ Xext) {
    const float* X = (SRC == 0) ? Xext : g_out;
    float* mu = (SRC == 0) ? g_mu1 : g_mu2;
    float* rs = (SRC == 0) ? g_rs1 : g_rs2;
    int gp = blockIdx.x * 32 + (threadIdx.x & 31);
    int grp = threadIdx.x >> 5;
    int b = gp / FHW_, p = gp % FHW_;
    const float* base = X + (long)b * C_ * FHW_ + p;
    float s = 0.f, ss = 0.f;
    for (int c = grp; c < C_; c += 8) { float v = base[(long)c * FHW_]; s += v; ss += v * v; }
    __shared__ float Ss[8][32], S2[8][32];
    Ss[grp][threadIdx.x & 31] = s; S2[grp][threadIdx.x & 31] = ss;
    __syncthreads();
    if (grp == 0) {
        for (int g = 1; g < 8; g++) { s += Ss[g][threadIdx.x & 31]; ss += S2[g][threadIdx.x & 31]; }
        float m = s / C_, v = ss / C_ - m * m;
        mu[gp] = m; rs[gp] = rsqrtf(v + 1e-6f);
    }
}

// layernorm + transpose to pixel-major bf16
template<int SRC>
__global__ void lnT_k(const float* __restrict__ Xext,
                      const float* __restrict__ w, const float* __restrict__ b) {
    const float* X  = (SRC == 0) ? Xext : g_out;
    const float* mu = (SRC == 0) ? g_mu1 : g_mu2;
    const float* rs = (SRC == 0) ? g_rs1 : g_rs2;
    __nv_bfloat16* T = (SRC == 0) ? g_lnimgT : g_lnoutT;
    int bz = blockIdx.z, n0 = blockIdx.x * 32, c0 = blockIdx.y * 64;
    __shared__ float t[64][33];
    const float* Xb = X + (long)bz * 442368;
    int nn = threadIdx.x & 31, cc = threadIdx.x >> 5;
    #pragma unroll
    for (int i = 0; i < 8; i++)
        t[cc + i * 8][nn] = Xb[(long)(c0 + cc + i * 8) * 576 + n0 + nn];
    __syncthreads();
    int c = threadIdx.x & 63, nn2 = threadIdx.x >> 6;
    #pragma unroll
    for (int i = 0; i < 8; i++) {
        int n = n0 + nn2 + i * 4;
        float m = mu[bz * 576 + n], r = rs[bz * 576 + n];
        float v = (t[c][n - n0] - m) * r * w[c0 + c] + b[c0 + c];
        T[(long)bz * 442368 + (long)n * 768 + c0 + c] = __float2bfloat16(v);
    }
}

template<int W>
__global__ void cast_k(const float* __restrict__ src) {
    __nv_bfloat16* dst = (W == 0) ? g_wqkv : (W == 1) ? g_woimg : (W == 2) ? g_woimg2 :
                         (W == 3) ? g_wfc1 : g_wfc2;
    const int n = (W == 0) ? 2304 * 768 : (W == 2) ? 576 * 192 : 768 * 768;
    int i = blockIdx.x * 1024 + threadIdx.x;
    #pragma unroll
    for (int k = 0; k < 4; k++) {
        int idx = i + k * 256;
        if (idx < n) dst[idx] = __float2bfloat16(src[idx]);
    }
}

__device__ __forceinline__ float bred192(float v, int op, float* sh) {
    for (int o = 16; o; o >>= 1) {
        float t = __shfl_down_sync(~0u, v, o);
        v = op ? fmaxf(v, t) : v + t;
    }
    int w = threadIdx.x >> 5;
    if ((threadIdx.x & 31) == 0) sh[w] = v;
    __syncthreads();
    float r = sh[0];
    for (int i = 1; i < 6; i++) r = op ? fmaxf(r, sh[i]) : r + sh[i];
    __syncthreads();
    return r;
}

__global__ void attn_k() {
    int bid = blockIdx.x;
    int hd = bid % 192, n = (bid / 192) % 4, b = bid / 768;
    const float* qrow = g_qk + ((long)b * 1536 + n * 192 + hd) * 576;
    const float* krow = qrow + 768L * 576;
    int tid = threadIdx.x;
    float q0 = qrow[tid], q1 = qrow[tid + 192], q2 = qrow[tid + 384];
    float k0 = krow[tid], k1 = krow[tid + 192], k2 = krow[tid + 384];
    __shared__ float sh[6];
    float sumq = bred192(q0*q0 + q1*q1 + q2*q2, 0, sh);
    float sumk = bred192(k0*k0 + k1*k1 + k2*k2, 0, sh);
    float rq = 1.f / fmaxf(sqrtf(sumq), 1e-12f);
    float rk = 1.f / fmaxf(sqrtf(sumk), 1e-12f);
    float sgq = g_sq[(b * 4 + n) * 192 + hd];
    float sgk = g_sk[(b * 4 + n) * 192 + hd];
    float a0 = sgq * k0 * rk, a1 = sgq * k1 * rk, a2 = sgq * k2 * rk;
    float c0 = sgk * q0 * rq, c1 = sgk * q1 * rq, c2 = sgk * q2 * rq;
    float M1 = bred192(fmaxf(a0, fmaxf(a1, a2)), 1, sh);
    float e0 = __expf(a0 - M1), e1 = __expf(a1 - M1), e2 = __expf(a2 - M1);
    float S1 = bred192(e0 + e1 + e2, 0, sh);
    float M2 = bred192(fmaxf(c0, fmaxf(c1, c2)), 1, sh);
    float f0 = __expf(c0 - M2), f1 = __expf(c1 - M2), f2 = __expf(c2 - M2);
    float S2 = bred192(f0 + f1 + f2, 0, sh);
    float i1 = 1.f / S1, i2 = 1.f / S2;
    __nv_bfloat16* o = g_attn + (long)(b * 4 + n) * 147456 + (long)hd * 576;
    o[tid]       = __float2bfloat16(e0 * i1 + f0 * i2);
    o[tid + 192] = __float2bfloat16(e1 * i1 + f1 * i2);
    o[tid + 384] = __float2bfloat16(e2 * i1 + f2 * i2);
}

// depthwise 3x3 + exact gelu: bf16 channel-major in, bf16 pixel-major out
__global__ void dwgelu2_k(const float* __restrict__ Wd) {
    int blk = blockIdx.x;
    int b = blk / 96, cg = blk % 96;
    __shared__ float p[8][578];
    __shared__ __nv_bfloat16 ob[576][8];
    __shared__ float w[8][9];
    const __nv_bfloat16* Zb = g_z1 + ((long)b * 768 + cg * 8) * 576;
    for (int i = threadIdx.x; i < 8 * 576; i += 256)
        p[i / 576][i % 576] = __bfloat162float(Zb[i]);
    if (threadIdx.x < 72)
        w[threadIdx.x / 9][threadIdx.x % 9] = Wd[(cg * 8 + threadIdx.x / 9) * 9 + threadIdx.x % 9];
    __syncthreads();
    for (int i = threadIdx.x; i < 8 * 576; i += 256) {
        int ch = i & 7, pix = i >> 3;
        int y = pix / 24, x = pix % 24;
        float acc = 0.f;
        #pragma unroll
        for (int dy = -1; dy <= 1; dy++)
            #pragma unroll
            for (int dx = -1; dx <= 1; dx++) {
                int yy = y + dy, xx = x + dx;
                if (yy >= 0 && yy < 24 && xx >= 0 && xx < 24)
                    acc = fmaf(w[ch][(dy + 1) * 3 + dx + 1], p[ch][yy * 24 + xx], acc);
            }
        float g = 0.5f * acc * (1.f + erff(acc * 0.70710678118654752f));
        ob[pix][ch] = __float2bfloat16(g);
    }
    __syncthreads();
    __nv_bfloat16* Ob = g_z2T + (long)b * 442368 + cg * 8;
    for (int pix = threadIdx.x; pix < 576; pix += 256)
        *(uint4*)(Ob + (long)pix * 768) = *(uint4*)&ob[pix][0];
}

// ---------------- warp-MMA bf16 GEMM (mma.sync, sm_80+ ISA) -------------------
// C[128 x 64] tile = A[M,K](K-major) x B[N,K]^T(K-major); batch z.
// 256 threads = 8 warps in 4(M) x 2(N); warp tile 32x32; BK=32.
// smem rows stride 80B (stride 5 mod 8 -> conflict-free ldmatrix).
#define ASTRIDE 80
#define ABYTES  10240          // 128 rows * 80
#define BBYTES  5120           // 64 rows * 80
#define BUFBYTES 15360

__device__ __forceinline__ uint32_t smem_u32(const void* p) {
    uint32_t a;
    asm("{ .reg .u64 t; cvta.to.shared.u64 t, %1; cvt.u32.u64 %0, t; }" : "=r"(a) : "l"(p));
    return a;
}
#define LDSM4(r0,r1,r2,r3,addr) \
    asm volatile("ldmatrix.sync.aligned.m8n8.x4.shared.b16 {%0,%1,%2,%3}, [%4];" \
        : "=r"(r0),"=r"(r1),"=r"(r2),"=r"(r3) : "r"(addr))
#define MMA16816(d,a,b0,b1) \
    asm volatile("mma.sync.aligned.m16n8k16.row.col.f32.bf16.bf16.f32 " \
        "{%0,%1,%2,%3},{%4,%5,%6,%7},{%8,%9},{%0,%1,%2,%3};" \
        : "+f"((d)[0]),"+f"((d)[1]),"+f"((d)[2]),"+f"((d)[3]) \
        : "r"((a)[0]),"r"((a)[1]),"r"((a)[2]),"r"((a)[3]),"r"(b0),"r"(b1))

template<int EPI>
__global__ void __launch_bounds__(256) mm_gemm(
    const float* __restrict__ biasM, const float* __restrict__ biasN,
    const float* __restrict__ resExt, float* __restrict__ f32o)
{
    constexpr int K   = (EPI == 1) ? 576 : (EPI == 2) ? 192 : 768;
    constexpr int nkb = K / 32;
    constexpr long sAz = (EPI == 1) ? 147456 : (EPI == 2) ? 147456 : 0;
    constexpr long sBz = (EPI == 0) ? 442368 : (EPI == 1) ? 110592 : (EPI == 2) ? 0 : 442368;

    const __nv_bfloat16* Aop =
        (EPI == 0) ? g_wqkv : (EPI == 1) ? g_attn : (EPI == 2) ? g_img :
        (EPI == 3) ? g_woimg : (EPI == 4) ? g_wfc1 : g_wfc2;
    const __nv_bfloat16* Bop =
        (EPI == 0) ? g_lnimgT : (EPI == 1) ? g_v : (EPI == 2) ? g_woimg2 :
        (EPI == 3) ? g_yT : (EPI == 4) ? g_lnoutT : g_z2T;

    __shared__ __align__(16) char sm[2][BUFBYTES];

    int tid = threadIdx.x, lane = tid & 31, wid = tid >> 5;
    int wm = wid & 3, wn = wid >> 2;
    int z = blockIdx.z, m0 = blockIdx.y * 128, n0 = blockIdx.x * 64;
    const __nv_bfloat16* Ab = Aop + sAz * z + (long)m0 * K;
    const __nv_bfloat16* Bb = Bop + sBz * z + (long)n0 * K;
    uint32_t sbase = smem_u32(sm);

    const int srow = tid >> 2, sch = tid & 3;

    float acc[2][4][4];
    #pragma unroll
    for (int i = 0; i < 2; i++)
        #pragma unroll
        for (int j = 0; j < 4; j++)
            #pragma unroll
            for (int k = 0; k < 4; k++) acc[i][j][k] = 0.f;

    uint4 pa0, pa1, pb0;
    // prologue: load + stage tile 0
    pa0 = *(const uint4*)(Ab + (long)srow * K + sch * 8);
    pa1 = *(const uint4*)(Ab + (long)(srow + 64) * K + sch * 8);
    pb0 = *(const uint4*)(Bb + (long)srow * K + sch * 8);
    *(uint4*)(sm[0] + srow * ASTRIDE + sch * 16) = pa0;
    *(uint4*)(sm[0] + (srow + 64) * ASTRIDE + sch * 16) = pa1;
    *(uint4*)(sm[0] + ABYTES + srow * ASTRIDE + sch * 16) = pb0;
    __syncthreads();

    for (int kb = 0; kb < nkb; kb++) {
        int buf = kb & 1;
        bool more = (kb + 1 < nkb);
        if (more) {
            const __nv_bfloat16* Ak = Ab + (kb + 1) * 32;
            const __nv_bfloat16* Bk = Bb + (kb + 1) * 32;
            pa0 = *(const uint4*)(Ak + (long)srow * K + sch * 8);
            pa1 = *(const uint4*)(Ak + (long)(srow + 64) * K + sch * 8);
            pb0 = *(const uint4*)(Bk + (long)srow * K + sch * 8);
        }
        uint32_t abase = sbase + buf * BUFBYTES + (wm * 32) * ASTRIDE;
        uint32_t bbase = sbase + buf * BUFBYTES + ABYTES + (wn * 32) * ASTRIDE;
        #pragma unroll
        for (int s = 0; s < 2; s++) {
            uint32_t afr[2][4], bfr[2][4];
            #pragma unroll
            for (int mi = 0; mi < 2; mi++) {
                uint32_t addr = abase + (mi * 16 + (lane & 15)) * ASTRIDE
                              + s * 32 + (lane >> 4) * 16;
                LDSM4(afr[mi][0], afr[mi][1], afr[mi][2], afr[mi][3], addr);
            }
            #pragma unroll
            for (int j = 0; j < 2; j++) {
                int nrow = j * 16 + (lane & 7) + ((lane >> 4) & 1) * 8;
                uint32_t addr = bbase + nrow * ASTRIDE + s * 32 + ((lane >> 3) & 1) * 16;
                LDSM4(bfr[j][0], bfr[j][1], bfr[j][2], bfr[j][3], addr);
            }
            #pragma unroll
            for (int mi = 0; mi < 2; mi++)
                #pragma unroll
                for (int ni = 0; ni < 4; ni++)
                    MMA16816(acc[mi][ni], afr[mi], bfr[ni >> 1][(ni & 1) * 2], bfr[ni >> 1][(ni & 1) * 2 + 1]);
        }
        if (more) {
            char* d = sm[buf ^ 1];
            *(uint4*)(d + srow * ASTRIDE + sch * 16) = pa0;
            *(uint4*)(d + (srow + 64) * ASTRIDE + sch * 16) = pa1;
            *(uint4*)(d + ABYTES + srow * ASTRIDE + sch * 16) = pb0;
            __syncthreads();
        }
    }

    // ---------------- epilogue ----------------
    const int mrow = m0 + wm * 32;
    const int ncol = n0 + wn * 32;
    #pragma unroll
    for (int mi = 0; mi < 2; mi++) {
        #pragma unroll
        for (int ni = 0; ni < 4; ni++) {
            int c = ncol + ni * 8 + 2 * (lane & 3);
            #pragma unroll
            for (int h = 0; h < 2; h++) {
                int r = mrow + mi * 16 + (lane >> 2) + h * 8;
                float f0 = acc[mi][ni][h * 2], f1 = acc[mi][ni][h * 2 + 1];
                if (EPI == 0) {
                    if (r < 1536) {
                        float2 v = { f0, f1 };
                        *(float2*)(g_qk + (long)z * 884736 + (long)r * 576 + c) = v;
                    } else {
                        __nv_bfloat162 v;
                        v.x = __float2bfloat16(f0); v.y = __float2bfloat16(f1);
                        *(__nv_bfloat162*)(g_v + (long)z * 442368 + (long)(r - 1536) * 576 + c) = v;
                    }
                } else if (EPI == 1) {
                    if (r < 192) {
                        int bz = z >> 2, nh = z & 3;
                        __nv_bfloat162 v;
                        v.x = __float2bfloat16(f0); v.y = __float2bfloat16(f1);
                        *(__nv_bfloat162*)(g_img + ((long)bz * 768 + nh * 192 + r) * 192 + c) = v;
                    }
                } else if (EPI == 2) {
                    g_yT[(long)z * 442368 + (long)c * 768 + r]       = __float2bfloat16(f0 + biasN[c]);
                    g_yT[(long)z * 442368 + (long)(c + 1) * 768 + r] = __float2bfloat16(f1 + biasN[c + 1]);
                } else if (EPI == 3) {
                    long o = (long)z * 442368 + (long)r * 576 + c;
                    float bm = biasM[r];
                    float2 rv = *(const float2*)(resExt + o);
                    float2 v = { f0 + bm + rv.x, f1 + bm + rv.y };
                    *(float2*)(g_out + o) = v;
                } else if (EPI == 4) {
                    __nv_bfloat162 v;
                    v.x = __float2bfloat16(f0); v.y = __float2bfloat16(f1);
                    *(__nv_bfloat162*)(g_z1 + (long)z * 442368 + (long)r * 576 + c) = v;
                } else {
                    long o = (long)z * 442368 + (long)r * 576 + c;
                    float2 rv = *(const float2*)(g_out + o);
                    float2 v = { f0 + rv.x, f1 + rv.y };
                    *(float2*)(f32o + o) = v;
                }
            }
        }
    }
}

// ---------------- host launch --------------------------------------------------
extern "C" void kernel_launch(void* const* d_in, const int* in_sizes, int n_in,
                              void* d_out, int out_size) {
    const float* img    = (const float*)d_in[0];
    const float* txt    = (const float*)d_in[1];
    const float* fn_w   = (const float*)d_in[2];
    const float* fn_b   = (const float*)d_in[3];
    const float* gn_w   = (const float*)d_in[4];
    const float* gn_b   = (const float*)d_in[5];
    const float* qkv_img_w = (const float*)d_in[6];
    const float* qkv_txt_w = (const float*)d_in[7];
    const float* o_img_w   = (const float*)d_in[8];
    const float* o_img_b   = (const float*)d_in[9];
    const float* o_img2_w  = (const float*)d_in[10];
    const float* o_img2_b  = (const float*)d_in[11];
    const float* ffn_w  = (const float*)d_in[12];
    const float* ffn_b  = (const float*)d_in[13];
    const float* fc1_w  = (const float*)d_in[14];
    const float* dw_w   = (const float*)d_in[15];
    const float* fc2_w  = (const float*)d_in[16];
    float* out_p = (float*)d_out;

    cast_k<0><<<1728, 256>>>(qkv_img_w);
    cast_k<1><<<576, 256>>>(o_img_w);
    cast_k<2><<<108, 256>>>(o_img2_w);
    cast_k<3><<<576, 256>>>(fc1_w);
    cast_k<4><<<576, 256>>>(fc2_w);

    txtln_k<<<32, 256>>>(txt, gn_w, gn_b);
    txtqkv_k<<<dim3(32, 6), 256>>>(qkv_txt_w);
    stats_k<0><<<(B_ * FHW_) / 32, 256>>>(img);
    lnT_k<0><<<dim3(18, 12, 32), 256>>>(img, fn_w, fn_b);

    // qkv projection: M=2304, N=576, K=768
    mm_gemm<0><<<dim3(9, 18, 32), 256>>>(nullptr, nullptr, nullptr, nullptr);
    attn_k<<<B_ * NH_ * HD_, 192>>>();
    // (attn1+attn2) @ V^T: M=256(pad), N=192, K=576, batch=128
    mm_gemm<1><<<dim3(3, 2, 128), 256>>>(nullptr, nullptr, nullptr, nullptr);
    // img @ o_img2_w^T + b2 -> yT: M=768, N=576, K=192
    mm_gemm<2><<<dim3(9, 6, 32), 256>>>(nullptr, o_img2_b, nullptr, nullptr);
    // o_img conv1x1 + bias + residual(img) -> g_out: M=768, N=576, K=768
    mm_gemm<3><<<dim3(9, 6, 32), 256>>>(o_img_b, nullptr, img, nullptr);
    stats_k<1><<<(B_ * FHW_) / 32, 256>>>(nullptr);
    lnT_k<1><<<dim3(18, 12, 32), 256>>>(nullptr, ffn_w, ffn_b);
    // fc1: M=768, N=576, K=768
    mm_gemm<4><<<dim3(9, 6, 32), 256>>>(nullptr, nullptr, nullptr, nullptr);
    dwgelu2_k<<<B_ * 96, 256>>>(dw_w);
    // fc2 + residual(g_out) -> d_out
    mm_gemm<5><<<dim3(9, 6, 32), 256>>>(nullptr, nullptr, nullptr, out_p);
}

// round 5
// speedup vs baseline: 6.8062x; 1.2810x over previous
#include <cuda_runtime.h>
#include <cuda_bf16.h>
#include <math.h>
#include <stdint.h>

#define B_   32
#define C_   768
#define D_   512
#define NH_  4
#define HD_  192
#define FHW_ 576

// ---------------- device scratch (zero-init, no runtime allocation) ----------
__device__ float g_tbuf[32*512];
__device__ float g_sq[32*4*192], g_sk[32*4*192];
__device__ float g_mu1[18432], g_rs1[18432], g_mu2[18432], g_rs2[18432];
__device__ float g_rsumWo[768];
__device__ float g_qk[32L*1536*576];              // q,k fp32 channel-major
__device__ float g_out[32L*768*576];              // attn-block output fp32
__device__ __nv_bfloat16 g_wqkv[2304*768];
__device__ __nv_bfloat16 g_woimg[768*768];
__device__ __nv_bfloat16 g_woimg2[576*192];
__device__ __nv_bfloat16 g_wfc1[768*768];
__device__ __nv_bfloat16 g_wfc2[768*768];
__device__ __nv_bfloat16 g_lnimgT[32L*576*768];   // LN(img) pixel-major
__device__ __nv_bfloat16 g_v[32L*768*576];        // v bf16 channel-major
__device__ __nv_bfloat16 g_attn[128L*256*576];    // attn rows; rows 192..255 stay zero
__device__ __nv_bfloat16 g_imgT[32L*192*768];     // img transposed: [g][c]
__device__ __nv_bfloat16 g_T[32L*768*192];        // T = Wo @ img, row-major [o][g]
__device__ __nv_bfloat16 g_lnoutT[32L*576*768];   // LN(out) pixel-major
__device__ __nv_bfloat16 g_z1[32L*768*576];       // fc1 out channel-major
__device__ __nv_bfloat16 g_z2T[32L*576*768];      // dw+gelu pixel-major

// ---------------- small kernels ----------------------------------------------
__global__ void txtln_k(const float* __restrict__ T, const float* __restrict__ gw,
                        const float* __restrict__ gb) {
    int b = blockIdx.x, tid = threadIdx.x;
    const float* row = T + (long)b * D_;
    float s = 0.f, ss = 0.f;
    for (int i = tid; i < D_; i += 256) { float v = row[i]; s += v; ss += v * v; }
    for (int o = 16; o; o >>= 1) { s += __shfl_down_sync(~0u, s, o); ss += __shfl_down_sync(~0u, ss, o); }
    __shared__ float red[16]; __shared__ float mr[2];
    int w = tid >> 5;
    if ((tid & 31) == 0) { red[w] = s; red[8 + w] = ss; }
    __syncthreads();
    if (tid == 0) {
        float S = 0.f, S2 = 0.f;
        for (int i = 0; i < 8; i++) { S += red[i]; S2 += red[8 + i]; }
        float m = S / D_, v = S2 / D_ - m * m;
        mr[0] = m; mr[1] = rsqrtf(v + 1e-5f);
    }
    __syncthreads();
    float m = mr[0], r = mr[1];
    for (int i = tid; i < D_; i += 256)
        g_tbuf[(long)b * D_ + i] = (row[i] - m) * r * gw[i] + gb[i];
}

__global__ void txtqkv_k(const float* __restrict__ Wq) {
    int b = blockIdx.x;
    __shared__ float t[512];
    for (int i = threadIdx.x; i < 512; i += 256) t[i] = g_tbuf[(long)b * 512 + i];
    __syncthreads();
    int idx = blockIdx.y * 256 + threadIdx.x;
    int n = idx / 384, r = idx % 384, part = r / 192, hd = r % 192;
    const float* w = Wq + (long)(n * 576 + part * 192 + hd) * 512;
    float acc = 0.f;
    #pragma unroll 8
    for (int k2 = 0; k2 < 512; k2++) acc += t[k2] * w[k2];
    float sgn = acc / fmaxf(fabsf(acc), 1e-12f);
    if (part == 0) g_sq[(b * 4 + n) * 192 + hd] = sgn;
    else           g_sk[(b * 4 + n) * 192 + hd] = sgn;
}

__global__ void rowsum_k(const float* __restrict__ W) {
    int row = blockIdx.x * 8 + (threadIdx.x >> 5);
    int lane = threadIdx.x & 31;
    const float* p = W + (long)row * 768;
    float s = 0.f;
    for (int c = lane; c < 768; c += 32) s += p[c];
    for (int o = 16; o; o >>= 1) s += __shfl_down_sync(~0u, s, o);
    if (lane == 0) g_rsumWo[row] = s;
}

template<int SRC>
__global__ void stats_k(const float* __restrict__ Xext) {
    const float* X = (SRC == 0) ? Xext : g_out;
    float* mu = (SRC == 0) ? g_mu1 : g_mu2;
    float* rs = (SRC == 0) ? g_rs1 : g_rs2;
    int gp = blockIdx.x * 32 + (threadIdx.x & 31);
    int grp = threadIdx.x >> 5;
    int b = gp / FHW_, p = gp % FHW_;
    const float* base = X + (long)b * C_ * FHW_ + p;
    float s = 0.f, ss = 0.f;
    for (int c = grp; c < C_; c += 8) { float v = base[(long)c * FHW_]; s += v; ss += v * v; }
    __shared__ float Ss[8][32], S2[8][32];
    Ss[grp][threadIdx.x & 31] = s; S2[grp][threadIdx.x & 31] = ss;
    __syncthreads();
    if (grp == 0) {
        for (int g = 1; g < 8; g++) { s += Ss[g][threadIdx.x & 31]; ss += S2[g][threadIdx.x & 31]; }
        float m = s / C_, v = ss / C_ - m * m;
        mu[gp] = m; rs[gp] = rsqrtf(v + 1e-6f);
    }
}

template<int SRC>
__global__ void lnT_k(const float* __restrict__ Xext,
                      const float* __restrict__ w, const float* __restrict__ b) {
    const float* X  = (SRC == 0) ? Xext : g_out;
    const float* mu = (SRC == 0) ? g_mu1 : g_mu2;
    const float* rs = (SRC == 0) ? g_rs1 : g_rs2;
    __nv_bfloat16* T = (SRC == 0) ? g_lnimgT : g_lnoutT;
    int bz = blockIdx.z, n0 = blockIdx.x * 32, c0 = blockIdx.y * 64;
    __shared__ float t[64][33];
    const float* Xb = X + (long)bz * 442368;
    int nn = threadIdx.x & 31, cc = threadIdx.x >> 5;
    #pragma unroll
    for (int i = 0; i < 8; i++)
        t[cc + i * 8][nn] = Xb[(long)(c0 + cc + i * 8) * 576 + n0 + nn];
    __syncthreads();
    int c = threadIdx.x & 63, nn2 = threadIdx.x >> 6;
    #pragma unroll
    for (int i = 0; i < 8; i++) {
        int n = n0 + nn2 + i * 4;
        float m = mu[bz * 576 + n], r = rs[bz * 576 + n];
        float v = (t[c][n - n0] - m) * r * w[c0 + c] + b[c0 + c];
        T[(long)bz * 442368 + (long)n * 768 + c0 + c] = __float2bfloat16(v);
    }
}

template<int W>
__global__ void cast_k(const float* __restrict__ src) {
    __nv_bfloat16* dst = (W == 0) ? g_wqkv : (W == 1) ? g_woimg : (W == 2) ? g_woimg2 :
                         (W == 3) ? g_wfc1 : g_wfc2;
    const int n = (W == 0) ? 2304 * 768 : (W == 2) ? 576 * 192 : 768 * 768;
    int i = blockIdx.x * 1024 + threadIdx.x;
    #pragma unroll
    for (int k = 0; k < 4; k++) {
        int idx = i + k * 256;
        if (idx < n) dst[idx] = __float2bfloat16(src[idx]);
    }
}

__device__ __forceinline__ float bred192(float v, int op, float* sh) {
    for (int o = 16; o; o >>= 1) {
        float t = __shfl_down_sync(~0u, v, o);
        v = op ? fmaxf(v, t) : v + t;
    }
    int w = threadIdx.x >> 5;
    if ((threadIdx.x & 31) == 0) sh[w] = v;
    __syncthreads();
    float r = sh[0];
    for (int i = 1; i < 6; i++) r = op ? fmaxf(r, sh[i]) : r + sh[i];
    __syncthreads();
    return r;
}

__global__ void attn_k() {
    int bid = blockIdx.x;
    int hd = bid % 192, n = (bid / 192) % 4, b = bid / 768;
    const float* qrow = g_qk + ((long)b * 1536 + n * 192 + hd) * 576;
    const float* krow = qrow + 768L * 576;
    int tid = threadIdx.x;
    float q0 = qrow[tid], q1 = qrow[tid + 192], q2 = qrow[tid + 384];
    float k0 = krow[tid], k1 = krow[tid + 192], k2 = krow[tid + 384];
    __shared__ float sh[6];
    float sumq = bred192(q0*q0 + q1*q1 + q2*q2, 0, sh);
    float sumk = bred192(k0*k0 + k1*k1 + k2*k2, 0, sh);
    float rq = 1.f / fmaxf(sqrtf(sumq), 1e-12f);
    float rk = 1.f / fmaxf(sqrtf(sumk), 1e-12f);
    float sgq = g_sq[(b * 4 + n) * 192 + hd];
    float sgk = g_sk[(b * 4 + n) * 192 + hd];
    float a0 = sgq * k0 * rk, a1 = sgq * k1 * rk, a2 = sgq * k2 * rk;
    float c0 = sgk * q0 * rq, c1 = sgk * q1 * rq, c2 = sgk * q2 * rq;
    float M1 = bred192(fmaxf(a0, fmaxf(a1, a2)), 1, sh);
    float e0 = __expf(a0 - M1), e1 = __expf(a1 - M1), e2 = __expf(a2 - M1);
    float S1 = bred192(e0 + e1 + e2, 0, sh);
    float M2 = bred192(fmaxf(c0, fmaxf(c1, c2)), 1, sh);
    float f0 = __expf(c0 - M2), f1 = __expf(c1 - M2), f2 = __expf(c2 - M2);
    float S2 = bred192(f0 + f1 + f2, 0, sh);
    float i1 = 1.f / S1, i2 = 1.f / S2;
    __nv_bfloat16* o = g_attn + (long)(b * 4 + n) * 147456 + (long)hd * 576;
    o[tid]       = __float2bfloat16(e0 * i1 + f0 * i2);
    o[tid + 192] = __float2bfloat16(e1 * i1 + f1 * i2);
    o[tid + 384] = __float2bfloat16(e2 * i1 + f2 * i2);
}

__global__ void dwgelu2_k(const float* __restrict__ Wd) {
    int blk = blockIdx.x;
    int b = blk / 96, cg = blk % 96;
    __shared__ float p[8][578];
    __shared__ __nv_bfloat16 ob[576][8];
    __shared__ float w[8][9];
    const __nv_bfloat16* Zb = g_z1 + ((long)b * 768 + cg * 8) * 576;
    for (int i = threadIdx.x; i < 8 * 576; i += 256)
        p[i / 576][i % 576] = __bfloat162float(Zb[i]);
    if (threadIdx.x < 72)
        w[threadIdx.x / 9][threadIdx.x % 9] = Wd[(cg * 8 + threadIdx.x / 9) * 9 + threadIdx.x % 9];
    __syncthreads();
    for (int i = threadIdx.x; i < 8 * 576; i += 256) {
        int ch = i & 7, pix = i >> 3;
        int y = pix / 24, x = pix % 24;
        float acc = 0.f;
        #pragma unroll
        for (int dy = -1; dy <= 1; dy++)
            #pragma unroll
            for (int dx = -1; dx <= 1; dx++) {
                int yy = y + dy, xx = x + dx;
                if (yy >= 0 && yy < 24 && xx >= 0 && xx < 24)
                    acc = fmaf(w[ch][(dy + 1) * 3 + dx + 1], p[ch][yy * 24 + xx], acc);
            }
        float g = 0.5f * acc * (1.f + erff(acc * 0.70710678118654752f));
        ob[pix][ch] = __float2bfloat16(g);
    }
    __syncthreads();
    __nv_bfloat16* Ob = g_z2T + (long)b * 442368 + cg * 8;
    for (int pix = threadIdx.x; pix < 576; pix += 256)
        *(uint4*)(Ob + (long)pix * 768) = *(uint4*)&ob[pix][0];
}

// ---------------- warp-MMA bf16 GEMM, cp.async 4-stage pipeline ---------------
// C[128 x 96] = A[M,K](K-major) x B[N,K]^T(K-major); batch z.
// 256 threads = 8 warps 4(M)x2(N); warp tile 32x48; BK=32; 4 stages.
#define ASTRIDE 80
#define STAGEB  17920          // 224 rows * 80

__device__ __forceinline__ uint32_t smem_u32(const void* p) {
    uint32_t a;
    asm("{ .reg .u64 t; cvta.to.shared.u64 t, %1; cvt.u32.u64 %0, t; }" : "=r"(a) : "l"(p));
    return a;
}
#define LDSM4(r0,r1,r2,r3,addr) \
    asm volatile("ldmatrix.sync.aligned.m8n8.x4.shared.b16 {%0,%1,%2,%3}, [%4];" \
        : "=r"(r0),"=r"(r1),"=r"(r2),"=r"(r3) : "r"(addr))
#define MMA16816(d,a,b0,b1) \
    asm volatile("mma.sync.aligned.m16n8k16.row.col.f32.bf16.bf16.f32 " \
        "{%0,%1,%2,%3},{%4,%5,%6,%7},{%8,%9},{%0,%1,%2,%3};" \
        : "+f"((d)[0]),"+f"((d)[1]),"+f"((d)[2]),"+f"((d)[3]) \
        : "r"((a)[0]),"r"((a)[1]),"r"((a)[2]),"r"((a)[3]),"r"(b0),"r"(b1))
#define CPA16(dst, src) \
    asm volatile("cp.async.cg.shared.global [%0], [%1], 16;" :: "r"(dst), "l"(src))
#define CP_COMMIT() asm volatile("cp.async.commit_group;")
#define CP_WAIT2()  asm volatile("cp.async.wait_group 2;")

template<int EPI>
__global__ void __launch_bounds__(256) mm_gemm(
    const float* __restrict__ biasM, const float* __restrict__ biasN,
    const float* __restrict__ resExt, float* __restrict__ f32o)
{
    constexpr int K   = (EPI == 1) ? 576 : (EPI == 3) ? 192 : 768;
    constexpr int nkb = K / 32;
    constexpr long sAz = (EPI == 1) ? 147456 : (EPI == 3) ? 147456 : 0;
    constexpr long sBz = (EPI == 0) ? 442368 : (EPI == 1) ? 110592 :
                         (EPI == 2) ? 147456 : (EPI == 3) ? 0 : 442368;

    const __nv_bfloat16* Aop =
        (EPI == 0) ? g_wqkv : (EPI == 1) ? g_attn : (EPI == 2) ? g_woimg :
        (EPI == 3) ? g_T : (EPI == 4) ? g_wfc1 : g_wfc2;
    const __nv_bfloat16* Bop =
        (EPI == 0) ? g_lnimgT : (EPI == 1) ? g_v : (EPI == 2) ? g_imgT :
        (EPI == 3) ? g_woimg2 : (EPI == 4) ? g_lnoutT : g_z2T;

    extern __shared__ __align__(16) char sm[];
    uint32_t sbase = smem_u32(sm);

    int tid = threadIdx.x, lane = tid & 31, wid = tid >> 5;
    int wm = wid & 3, wn = wid >> 2;
    int z = blockIdx.z, m0 = blockIdx.y * 128, n0 = blockIdx.x * 96;
    const __nv_bfloat16* Ab = Aop + sAz * z + (long)m0 * K;
    const __nv_bfloat16* Bb = Bop + sBz * z + (long)n0 * K;

    float acc[2][6][4];
    #pragma unroll
    for (int i = 0; i < 2; i++)
        #pragma unroll
        for (int j = 0; j < 6; j++)
            #pragma unroll
            for (int k = 0; k < 4; k++) acc[i][j][k] = 0.f;

    // stage loader: 224 rows x 4 chunks of 16B
    auto load_stage = [&](int slot, int kblk) {
        uint32_t sd = sbase + slot * STAGEB;
        const __nv_bfloat16* Akp = Ab + kblk * 32;
        const __nv_bfloat16* Bkp = Bb + kblk * 32;
        #pragma unroll
        for (int it = 0; it < 4; it++) {
            int i = tid + it * 256;
            if (it < 3 || tid < 128) {
                int row = i >> 2, ch = i & 3;
                const __nv_bfloat16* src = (row < 128)
                    ? (Akp + (long)row * K + ch * 8)
                    : (Bkp + (long)(row - 128) * K + ch * 8);
                CPA16(sd + row * ASTRIDE + ch * 16, src);
            }
        }
    };

    #pragma unroll
    for (int s = 0; s < 3; s++) { load_stage(s, s); CP_COMMIT(); }

    for (int kb = 0; kb < nkb; kb++) {
        CP_WAIT2();
        __syncthreads();
        int nxt = kb + 3;
        if (nxt < nkb) load_stage(nxt & 3, nxt);
        CP_COMMIT();

        int buf = kb & 3;
        uint32_t abase = sbase + buf * STAGEB + (wm * 32) * ASTRIDE;
        uint32_t bbase = sbase + buf * STAGEB + 128 * ASTRIDE + (wn * 48) * ASTRIDE;
        #pragma unroll
        for (int s = 0; s < 2; s++) {
            uint32_t afr[2][4], bfr[3][4];
            #pragma unroll
            for (int mi = 0; mi < 2; mi++) {
                uint32_t addr = abase + (mi * 16 + (lane & 15)) * ASTRIDE
                              + s * 32 + (lane >> 4) * 16;
                LDSM4(afr[mi][0], afr[mi][1], afr[mi][2], afr[mi][3], addr);
            }
            #pragma unroll
            for (int j = 0; j < 3; j++) {
                int nrow = j * 16 + (lane & 7) + ((lane >> 4) & 1) * 8;
                uint32_t addr = bbase + nrow * ASTRIDE + s * 32 + ((lane >> 3) & 1) * 16;
                LDSM4(bfr[j][0], bfr[j][1], bfr[j][2], bfr[j][3], addr);
            }
            #pragma unroll
            for (int mi = 0; mi < 2; mi++)
                #pragma unroll
                for (int ni = 0; ni < 6; ni++)
                    MMA16816(acc[mi][ni], afr[mi], bfr[ni >> 1][(ni & 1) * 2], bfr[ni >> 1][(ni & 1) * 2 + 1]);
        }
    }

    // ---------------- epilogue ----------------
    const int mrow = m0 + wm * 32;
    const int ncol = n0 + wn * 48;
    #pragma unroll
    for (int mi = 0; mi < 2; mi++) {
        #pragma unroll
        for (int ni = 0; ni < 6; ni++) {
            int c = ncol + ni * 8 + 2 * (lane & 3);
            #pragma unroll
            for (int h = 0; h < 2; h++) {
                int r = mrow + mi * 16 + (lane >> 2) + h * 8;
                float f0 = acc[mi][ni][h * 2], f1 = acc[mi][ni][h * 2 + 1];
                if (EPI == 0) {
                    if (r < 1536) {
                        float2 v = { f0, f1 };
                        *(float2*)(g_qk + (long)z * 884736 + (long)r * 576 + c) = v;
                    } else {
                        __nv_bfloat162 v;
                        v.x = __float2bfloat16(f0); v.y = __float2bfloat16(f1);
                        *(__nv_bfloat162*)(g_v + (long)z * 442368 + (long)(r - 1536) * 576 + c) = v;
                    }
                } else if (EPI == 1) {
                    if (r < 192) {
                        int bz = z >> 2, nh = z & 3;
                        long base = (long)bz * 147456 + nh * 192 + r;
                        g_imgT[base + (long)c * 768]       = __float2bfloat16(f0);
                        g_imgT[base + (long)(c + 1) * 768] = __float2bfloat16(f1);
                    }
                } else if (EPI == 2) {
                    __nv_bfloat162 v;
                    v.x = __float2bfloat16(f0); v.y = __float2bfloat16(f1);
                    *(__nv_bfloat162*)(g_T + (long)z * 147456 + (long)r * 192 + c) = v;
                } else if (EPI == 3) {
                    long o = (long)z * 442368 + (long)r * 576 + c;
                    float bm = biasM[r], rsum = g_rsumWo[r];
                    float2 rv = *(const float2*)(resExt + o);
                    float2 v = { f0 + bm + rsum * biasN[c] + rv.x,
                                 f1 + bm + rsum * biasN[c + 1] + rv.y };
                    *(float2*)(g_out + o) = v;
                } else if (EPI == 4) {
                    __nv_bfloat162 v;
                    v.x = __float2bfloat16(f0); v.y = __float2bfloat16(f1);
                    *(__nv_bfloat162*)(g_z1 + (long)z * 442368 + (long)r * 576 + c) = v;
                } else {
                    long o = (long)z * 442368 + (long)r * 576 + c;
                    float2 rv = *(const float2*)(g_out + o);
                    float2 v = { f0 + rv.x, f1 + rv.y };
                    *(float2*)(f32o + o) = v;
                }
            }
        }
    }
}

// ---------------- host launch --------------------------------------------------
extern "C" void kernel_launch(void* const* d_in, const int* in_sizes, int n_in,
                              void* d_out, int out_size) {
    const float* img    = (const float*)d_in[0];
    const float* txt    = (const float*)d_in[1];
    const float* fn_w   = (const float*)d_in[2];
    const float* fn_b   = (const float*)d_in[3];
    const float* gn_w   = (const float*)d_in[4];
    const float* gn_b   = (const float*)d_in[5];
    const float* qkv_img_w = (const float*)d_in[6];
    const float* qkv_txt_w = (const float*)d_in[7];
    const float* o_img_w   = (const float*)d_in[8];
    const float* o_img_b   = (const float*)d_in[9];
    const float* o_img2_w  = (const float*)d_in[10];
    const float* o_img2_b  = (const float*)d_in[11];
    const float* ffn_w  = (const float*)d_in[12];
    const float* ffn_b  = (const float*)d_in[13];
    const float* fc1_w  = (const float*)d_in[14];
    const float* dw_w   = (const float*)d_in[15];
    const float* fc2_w  = (const float*)d_in[16];
    float* out_p = (float*)d_out;

    const int SMEM = 4 * STAGEB;  // 71680
    cudaFuncSetAttribute(mm_gemm<0>, cudaFuncAttributeMaxDynamicSharedMemorySize, SMEM);
    cudaFuncSetAttribute(mm_gemm<1>, cudaFuncAttributeMaxDynamicSharedMemorySize, SMEM);
    cudaFuncSetAttribute(mm_gemm<2>, cudaFuncAttributeMaxDynamicSharedMemorySize, SMEM);
    cudaFuncSetAttribute(mm_gemm<3>, cudaFuncAttributeMaxDynamicSharedMemorySize, SMEM);
    cudaFuncSetAttribute(mm_gemm<4>, cudaFuncAttributeMaxDynamicSharedMemorySize, SMEM);
    cudaFuncSetAttribute(mm_gemm<5>, cudaFuncAttributeMaxDynamicSharedMemorySize, SMEM);

    cast_k<0><<<1728, 256>>>(qkv_img_w);
    cast_k<1><<<576, 256>>>(o_img_w);
    cast_k<2><<<108, 256>>>(o_img2_w);
    cast_k<3><<<576, 256>>>(fc1_w);
    cast_k<4><<<576, 256>>>(fc2_w);
    rowsum_k<<<96, 256>>>(o_img_w);

    txtln_k<<<32, 256>>>(txt, gn_w, gn_b);
    txtqkv_k<<<dim3(32, 6), 256>>>(qkv_txt_w);
    stats_k<0><<<(B_ * FHW_) / 32, 256>>>(img);
    lnT_k<0><<<dim3(18, 12, 32), 256>>>(img, fn_w, fn_b);

    // qkv projection: M=2304, N=576, K=768
    mm_gemm<0><<<dim3(6, 18, 32), 256, SMEM>>>(nullptr, nullptr, nullptr, nullptr);
    attn_k<<<B_ * NH_ * HD_, 192>>>();
    // (attn1+attn2) @ V^T -> imgT: M=256(pad), N=192, K=576, batch=128
    mm_gemm<1><<<dim3(2, 2, 128), 256, SMEM>>>(nullptr, nullptr, nullptr, nullptr);
    // T = Wo @ img^T: M=768, N=192, K=768
    mm_gemm<2><<<dim3(2, 6, 32), 256, SMEM>>>(nullptr, nullptr, nullptr, nullptr);
    // out = T @ W2^T + bO + rsumWo*b2 + img: M=768, N=576, K=192
    mm_gemm<3><<<dim3(6, 6, 32), 256, SMEM>>>(o_img_b, o_img2_b, img, nullptr);
    stats_k<1><<<(B_ * FHW_) / 32, 256>>>(nullptr);
    lnT_k<1><<<dim3(18, 12, 32), 256>>>(nullptr, ffn_w, ffn_b);
    // fc1: M=768, N=576, K=768
    mm_gemm<4><<<dim3(6, 6, 32), 256, SMEM>>>(nullptr, nullptr, nullptr, nullptr);
    dwgelu2_k<<<B_ * 96, 256>>>(dw_w);
    // fc2 + residual(g_out) -> d_out
    mm_gemm<5><<<dim3(6, 6, 32), 256, SMEM>>>(nullptr, nullptr, nullptr, out_p);
}